// round 16
// baseline (speedup 1.0000x reference)
#include <cuda_runtime.h>
#include <cuda_fp16.h>
#include <cstdint>

#define T_LEN 1024
#define NTH   256
#define HSTR  72         // halves per row (144 B = 9*16B): 16B-aligned, conflict-free

static __device__ __forceinline__ float tanhapx(float x) {
    float y;
    asm("tanh.approx.f32 %0, %1;" : "=f"(y) : "f"(x));
    return y;
}
static __device__ __forceinline__ uint32_t pack2w(float a, float b) {
    __half2 t = __halves2half2(__float2half_rn(a), __float2half_rn(b));
    return *(uint32_t*)&t;
}
// 64-col permutation: h col c -> fragment-vectorized position (validated R10+)
static __device__ __forceinline__ int perm64(int c) {
    return (((c & 7) >> 1) << 4) + ((c >> 4) << 2) + (((c >> 3) & 1) << 1) + (c & 1);
}
static __device__ __forceinline__ void mma16816(float* d, const uint32_t* a, const uint32_t* b) {
    asm volatile(
        "mma.sync.aligned.m16n8k16.row.col.f32.f16.f16.f32 "
        "{%0,%1,%2,%3}, {%4,%5,%6,%7}, {%8,%9}, {%0,%1,%2,%3};"
        : "+f"(d[0]), "+f"(d[1]), "+f"(d[2]), "+f"(d[3])
        : "r"(a[0]), "r"(a[1]), "r"(a[2]), "r"(a[3]), "r"(b[0]), "r"(b[1]));
}

__global__ void out_init(float* out, const float* fc_b, int n) {
    int i = blockIdx.x * blockDim.x + threadIdx.x;
    if (i < n) out[i] = fc_b[0];
}

__global__ __launch_bounds__(NTH, 1)
void bilstm_mma(const float* __restrict__ x,
                const float* __restrict__ Wih_f, const float* __restrict__ Whh_f,
                const float* __restrict__ bih_f, const float* __restrict__ bhh_f,
                const float* __restrict__ Wih_b, const float* __restrict__ Whh_b,
                const float* __restrict__ bih_b, const float* __restrict__ bhh_b,
                const float* __restrict__ fc_w, float* __restrict__ out)
{
    __shared__ __align__(16) __half hs[2][16][HSTR];   // h (fp16) in frag-permuted order
    __shared__ float psum[2][16][8];

    const int tid = threadIdx.x, wid = tid >> 5, lane = tid & 31;
    const int q = lane & 3, r = lane >> 2;
    const int dir = blockIdx.x & 1;
    const int b0 = (blockIdx.x >> 1) * 16;

    const float* Whh = dir ? Whh_b : Whh_f;
    const float* Wih = dir ? Wih_b : Wih_f;
    const float* bih = dir ? bih_b : bih_f;
    const float* bhh = dir ? bhh_b : bhh_f;

    for (int i = tid; i < 2 * 16 * HSTR; i += NTH) (&hs[0][0][0])[i] = __float2half(0.f);

    // ---- B fragments (Whh^T), fp16; sigmoid rows (i,f,o) pre-scaled by 0.5 ----
    // ---- bf4: extra k-step carrying [Wih | bias_hi | bias_lo | Wih] ----
    uint32_t bf[4][4][2];
    uint32_t bf4[4];
    {
        const int qp = r >> 1, odd = r & 1;
        #pragma unroll
        for (int nt = 0; nt < 4; ++nt) {
            const int unit = 8 * wid + (nt >= 2 ? 4 : 0) + qp;
            const int row = ((nt & 1) ? (odd ? 192 : 64) : (odd ? 128 : 0)) + unit;
            const bool isG = ((nt & 1) == 0) && odd;          // g-gate rows stay unscaled
            const float sc = isG ? 1.0f : 0.5f;
            const float* wr = Whh + row * 64;
            #pragma unroll
            for (int ks = 0; ks < 4; ++ks) {
                const int wcol = ks * 16 + q * 2;
                bf[ks][nt][0] = pack2w(sc * __ldg(wr + wcol),     sc * __ldg(wr + wcol + 1));
                bf[ks][nt][1] = pack2w(sc * __ldg(wr + wcol + 8), sc * __ldg(wr + wcol + 9));
            }
            const float ws = sc * Wih[row];
            const float bs = sc * (bih[row] + bhh[row]);
            const float bhi = __half2float(__float2half_rn(bs));
            const float blo = bs - bhi;
            if (q == 0)      bf4[nt] = pack2w(ws, bs);        // (Wih_s, bias_hi)
            else if (q == 1) bf4[nt] = pack2w(blo, ws);       // (bias_lo, Wih_s)
            else             bf4[nt] = 0u;
        }
    }

    // gate-owner: units u1 = 8*wid+q, u2 = u1+4; streams r, r+8
    const int u1 = 8 * wid + q, u2 = u1 + 4;
    const float fcw1 = fc_w[dir * 64 + u1], fcw2 = fc_w[dir * 64 + u2];
    const int pc1 = perm64(u1), pc2 = perm64(u2);

    float cc[4]   = {0.f, 0.f, 0.f, 0.f};
    float hval[4] = {0.f, 0.f, 0.f, 0.f};   // persists across the barrier
    __syncthreads();

    // x prefetch for t = 0
    const float* xr0 = x + (size_t)(b0 + r) * T_LEN;
    const float* xr1 = x + (size_t)(b0 + r + 8) * T_LEN;
    float xv0 = __ldg(xr0 + (dir ? T_LEN - 1 : 0));
    float xv1 = __ldg(xr1 + (dir ? T_LEN - 1 : 0));

    for (int t = 0; t < T_LEN; ++t) {
        // ---- prefetch x(t+1) ----
        float pxv0 = 0.f, pxv1 = 0.f;
        if (t + 1 < T_LEN) {
            const int nxt = dir ? (T_LEN - 2 - t) : (t + 1);
            pxv0 = __ldg(xr0 + nxt);
            pxv1 = __ldg(xr1 + nxt);
        }

        // ---- deferred fc reduce for hval(t-1): overlaps this step's LDS/HMMA ----
        if (t > 0) {
            float pr  = fcw1 * hval[0] + fcw2 * hval[2];
            float pr8 = fcw1 * hval[1] + fcw2 * hval[3];
            pr  += __shfl_xor_sync(0xffffffffu, pr, 1);
            pr  += __shfl_xor_sync(0xffffffffu, pr, 2);
            pr8 += __shfl_xor_sync(0xffffffffu, pr8, 1);
            pr8 += __shfl_xor_sync(0xffffffffu, pr8, 2);
            if (q == 0) {
                psum[(t - 1) & 1][r][wid] = pr;
                psum[(t - 1) & 1][r + 8][wid] = pr8;
            }
        }
        // ---- flush step t-2 (slot t&1, written at step t-1, barrier-ordered) ----
        if (t >= 2 && wid == 0 && lane < 16) {
            const float* ps = &psum[t & 1][lane][0];
            float s = 0.f;
            #pragma unroll
            for (int j = 0; j < 8; ++j) s += ps[j];
            atomicAdd(out + (size_t)(b0 + lane) * T_LEN + (t - 2), s);
        }

        // ---- extra k-step A fragment: [x_hi, 1, 1, x_lo] built in registers ----
        uint32_t af4[4];
        {
            const float xl0 = xv0 - __half2float(__float2half_rn(xv0));
            const float xl1 = xv1 - __half2float(__float2half_rn(xv1));
            if (q == 0)      { af4[0] = pack2w(xv0, 1.0f);  af4[1] = pack2w(xv1, 1.0f); }
            else if (q == 1) { af4[0] = pack2w(1.0f, xl0);  af4[1] = pack2w(1.0f, xl1); }
            else             { af4[0] = 0u; af4[1] = 0u; }
            af4[2] = 0u; af4[3] = 0u;
        }

        // ---- x/bias MMAs first (independent of LDS) ----
        float d[4][4] = {{0.f,0.f,0.f,0.f},{0.f,0.f,0.f,0.f},{0.f,0.f,0.f,0.f},{0.f,0.f,0.f,0.f}};
        #pragma unroll
        for (int nt = 0; nt < 4; ++nt) {
            const uint32_t b4[2] = {bf4[nt], 0u};
            mma16816(d[nt], af4, b4);
        }

        // ---- A fragments: 4x LDS.128 from permuted buffer ----
        const __half* hb = &hs[(t & 1) ^ 1][0][0];
        uint32_t af[4][4];
        {
            const uint4* p0 = (const uint4*)(hb + r * HSTR + q * 16);
            const uint4* p1 = (const uint4*)(hb + (r + 8) * HSTR + q * 16);
            #pragma unroll
            for (int m = 0; m < 2; ++m) {
                const uint4 v = p0[m];
                af[2*m][0] = v.x; af[2*m][2] = v.y; af[2*m+1][0] = v.z; af[2*m+1][2] = v.w;
                const uint4 u = p1[m];
                af[2*m][1] = u.x; af[2*m][3] = u.y; af[2*m+1][1] = u.z; af[2*m+1][3] = u.w;
            }
        }

        // ---- 16 Whh HMMAs ----
        #pragma unroll
        for (int ks = 0; ks < 4; ++ks) {
            mma16816(d[0], af[ks], bf[ks][0]);
            mma16816(d[1], af[ks], bf[ks][1]);
            mma16816(d[2], af[ks], bf[ks][2]);
            mma16816(d[3], af[ks], bf[ks][3]);
        }

        // ---- gates: z comes straight from HMMA (sigmoid rows pre-scaled) ----
        __half* hw = &hs[t & 1][0][0];
        #pragma unroll
        for (int cidx = 0; cidx < 4; ++cidx) {
            const bool isU2 = cidx >= 2;
            const int ti = isU2 ? 2 : 0;
            const int co = (cidx & 1) * 2;
            const float ig = fmaf(0.5f, tanhapx(d[ti][co]), 0.5f) * tanhapx(d[ti][co + 1]);
            const float ff = fmaf(0.5f, tanhapx(d[ti + 1][co]), 0.5f);
            cc[cidx] = fmaf(ff, cc[cidx], ig);
            hval[cidx] = fmaf(0.5f, tanhapx(d[ti + 1][co + 1]), 0.5f) * tanhapx(cc[cidx]);
            hw[((cidx & 1) ? (r + 8) : r) * HSTR + (isU2 ? pc2 : pc1)] = __float2half_rn(hval[cidx]);
        }

        xv0 = pxv0;
        xv1 = pxv1;
        __syncthreads();
    }

    // ---- tail: reduce hval(T-1), flush T-2 and T-1 ----
    {
        float pr  = fcw1 * hval[0] + fcw2 * hval[2];
        float pr8 = fcw1 * hval[1] + fcw2 * hval[3];
        pr  += __shfl_xor_sync(0xffffffffu, pr, 1);
        pr  += __shfl_xor_sync(0xffffffffu, pr, 2);
        pr8 += __shfl_xor_sync(0xffffffffu, pr8, 1);
        pr8 += __shfl_xor_sync(0xffffffffu, pr8, 2);
        if (q == 0) {
            psum[(T_LEN - 1) & 1][r][wid] = pr;
            psum[(T_LEN - 1) & 1][r + 8][wid] = pr8;
        }
    }
    if (wid == 0 && lane < 16) {
        const float* ps = &psum[T_LEN & 1][lane][0];
        float s = 0.f;
        #pragma unroll
        for (int j = 0; j < 8; ++j) s += ps[j];
        atomicAdd(out + (size_t)(b0 + lane) * T_LEN + (T_LEN - 2), s);
    }
    __syncthreads();
    if (wid == 0 && lane < 16) {
        const float* ps = &psum[(T_LEN - 1) & 1][lane][0];
        float s = 0.f;
        #pragma unroll
        for (int j = 0; j < 8; ++j) s += ps[j];
        atomicAdd(out + (size_t)(b0 + lane) * T_LEN + (T_LEN - 1), s);
    }
}

extern "C" void kernel_launch(void* const* d_in, const int* in_sizes, int n_in,
                              void* d_out, int out_size) {
    const float* x     = (const float*)d_in[0];
    const float* Wih_f = (const float*)d_in[1];
    const float* Whh_f = (const float*)d_in[2];
    const float* bih_f = (const float*)d_in[3];
    const float* bhh_f = (const float*)d_in[4];
    const float* Wih_b = (const float*)d_in[5];
    const float* Whh_b = (const float*)d_in[6];
    const float* bih_b = (const float*)d_in[7];
    const float* bhh_b = (const float*)d_in[8];
    const float* fc_w  = (const float*)d_in[9];
    const float* fc_b  = (const float*)d_in[10];
    float* out = (float*)d_out;

    out_init<<<(out_size + 255) / 256, 256>>>(out, fc_b, out_size);

    const int B = in_sizes[0] / T_LEN;   // 1024
    const int grid = (B / 16) * 2;       // 128 CTAs: (batch-group, direction)
    bilstm_mma<<<grid, NTH>>>(x, Wih_f, Whh_f, bih_f, bhh_f,
                              Wih_b, Whh_b, bih_b, bhh_b, fc_w, out);
    (void)n_in;
}

// round 17
// speedup vs baseline: 1.0635x; 1.0635x over previous
#include <cuda_runtime.h>
#include <cuda_fp16.h>
#include <cstdint>

#define T_LEN 1024
#define NTH   256
#define HSTR  72         // halves per row (144 B = 9*16B): 16B-aligned, conflict-free

static __device__ __forceinline__ float tanhapx(float x) {
    float y;
    asm("tanh.approx.f32 %0, %1;" : "=f"(y) : "f"(x));
    return y;
}
static __device__ __forceinline__ uint32_t pack2w(float a, float b) {
    __half2 t = __halves2half2(__float2half_rn(a), __float2half_rn(b));
    return *(uint32_t*)&t;
}
// 64-col permutation: h col c -> fragment-vectorized position (validated R10+)
static __device__ __forceinline__ int perm64(int c) {
    return (((c & 7) >> 1) << 4) + ((c >> 4) << 2) + (((c >> 3) & 1) << 1) + (c & 1);
}
static __device__ __forceinline__ void mma16816(float* d, const uint32_t* a, const uint32_t* b) {
    asm volatile(
        "mma.sync.aligned.m16n8k16.row.col.f32.f16.f16.f32 "
        "{%0,%1,%2,%3}, {%4,%5,%6,%7}, {%8,%9}, {%0,%1,%2,%3};"
        : "+f"(d[0]), "+f"(d[1]), "+f"(d[2]), "+f"(d[3])
        : "r"(a[0]), "r"(a[1]), "r"(a[2]), "r"(a[3]), "r"(b[0]), "r"(b[1]));
}

__global__ void out_init(float* out, const float* fc_b, int n) {
    int i = blockIdx.x * blockDim.x + threadIdx.x;
    if (i < n) out[i] = fc_b[0];
}

__global__ __launch_bounds__(NTH, 1)
void bilstm_mma(const float* __restrict__ x,
                const float* __restrict__ Wih_f, const float* __restrict__ Whh_f,
                const float* __restrict__ bih_f, const float* __restrict__ bhh_f,
                const float* __restrict__ Wih_b, const float* __restrict__ Whh_b,
                const float* __restrict__ bih_b, const float* __restrict__ bhh_b,
                const float* __restrict__ fc_w, float* __restrict__ out)
{
    __shared__ __align__(16) __half hs[2][16][HSTR];   // h (fp16) in frag-permuted order
    __shared__ float psum[2][16][8];

    const int tid = threadIdx.x, wid = tid >> 5, lane = tid & 31;
    const int q = lane & 3, r = lane >> 2;
    const int dir = blockIdx.x & 1;
    const int b0 = (blockIdx.x >> 1) * 16;

    const float* Whh = dir ? Whh_b : Whh_f;
    const float* Wih = dir ? Wih_b : Wih_f;
    const float* bih = dir ? bih_b : bih_f;
    const float* bhh = dir ? bhh_b : bhh_f;

    for (int i = tid; i < 2 * 16 * HSTR; i += NTH) (&hs[0][0][0])[i] = __float2half(0.f);

    // ---- B fragments (Whh^T), fp16; sigmoid rows (i,f,o) pre-scaled by 0.5 ----
    uint32_t bf[4][4][2];
    {
        const int qp = r >> 1, odd = r & 1;
        #pragma unroll
        for (int nt = 0; nt < 4; ++nt) {
            const int unit = 8 * wid + (nt >= 2 ? 4 : 0) + qp;
            const int row = ((nt & 1) ? (odd ? 192 : 64) : (odd ? 128 : 0)) + unit;
            const bool isG = ((nt & 1) == 0) && odd;          // g-gate rows stay unscaled
            const float sc = isG ? 1.0f : 0.5f;
            const float* wr = Whh + row * 64;
            #pragma unroll
            for (int ks = 0; ks < 4; ++ks) {
                const int wcol = ks * 16 + q * 2;
                bf[ks][nt][0] = pack2w(sc * __ldg(wr + wcol),     sc * __ldg(wr + wcol + 1));
                bf[ks][nt][1] = pack2w(sc * __ldg(wr + wcol + 8), sc * __ldg(wr + wcol + 9));
            }
        }
    }

    // gate-owner: units u1 = 8*wid+q, u2 = u1+4; streams r, r+8
    // sigmoid-gate scalar constants pre-scaled by 0.5 to match B pre-scale
    const int u1 = 8 * wid + q, u2 = u1 + 4;
    const float wi_i1 = 0.5f * Wih[u1], wi_f1 = 0.5f * Wih[64 + u1],
                wi_g1 = Wih[128 + u1],  wi_o1 = 0.5f * Wih[192 + u1];
    const float wi_i2 = 0.5f * Wih[u2], wi_f2 = 0.5f * Wih[64 + u2],
                wi_g2 = Wih[128 + u2],  wi_o2 = 0.5f * Wih[192 + u2];
    const float bi1 = 0.5f * (bih[u1] + bhh[u1]),        bf1 = 0.5f * (bih[64 + u1] + bhh[64 + u1]);
    const float bg1 = bih[128 + u1] + bhh[128 + u1];
    const float bo1 = 0.5f * (bih[192 + u1] + bhh[192 + u1]);
    const float bi2 = 0.5f * (bih[u2] + bhh[u2]),        bf2 = 0.5f * (bih[64 + u2] + bhh[64 + u2]);
    const float bg2 = bih[128 + u2] + bhh[128 + u2];
    const float bo2 = 0.5f * (bih[192 + u2] + bhh[192 + u2]);
    const float fcw1 = fc_w[dir * 64 + u1], fcw2 = fc_w[dir * 64 + u2];
    const int pc1 = perm64(u1), pc2 = perm64(u2);

    float cc[4]   = {0.f, 0.f, 0.f, 0.f};
    float hval[4] = {0.f, 0.f, 0.f, 0.f};   // persists across the barrier
    __syncthreads();

    // x prefetch for t = 0
    const float* xr0 = x + (size_t)(b0 + r) * T_LEN;
    const float* xr1 = x + (size_t)(b0 + r + 8) * T_LEN;
    float xv0 = __ldg(xr0 + (dir ? T_LEN - 1 : 0));
    float xv1 = __ldg(xr1 + (dir ? T_LEN - 1 : 0));

    for (int t = 0; t < T_LEN; ++t) {
        // ---- prefetch x(t+1) — hides L2 latency under this step's compute ----
        float pxv0 = 0.f, pxv1 = 0.f;
        if (t + 1 < T_LEN) {
            const int nxt = dir ? (T_LEN - 2 - t) : (t + 1);
            pxv0 = __ldg(xr0 + nxt);
            pxv1 = __ldg(xr1 + nxt);
        }

        // ---- deferred fc reduce for hval(t-1): overlaps this step's LDS/HMMA ----
        if (t > 0) {
            float pr  = fcw1 * hval[0] + fcw2 * hval[2];
            float pr8 = fcw1 * hval[1] + fcw2 * hval[3];
            pr  += __shfl_xor_sync(0xffffffffu, pr, 1);
            pr  += __shfl_xor_sync(0xffffffffu, pr, 2);
            pr8 += __shfl_xor_sync(0xffffffffu, pr8, 1);
            pr8 += __shfl_xor_sync(0xffffffffu, pr8, 2);
            if (q == 0) {
                psum[(t - 1) & 1][r][wid] = pr;
                psum[(t - 1) & 1][r + 8][wid] = pr8;
            }
        }
        // ---- flush step t-2 (slot t&1, written at step t-1, barrier-ordered) ----
        if (t >= 2 && wid == 0 && lane < 16) {
            const float* ps = &psum[t & 1][lane][0];
            float s = 0.f;
            #pragma unroll
            for (int j = 0; j < 8; ++j) s += ps[j];
            atomicAdd(out + (size_t)(b0 + lane) * T_LEN + (t - 2), s);
        }

        // ---- A fragments: 4x LDS.128 from permuted buffer ----
        const __half* hb = &hs[(t & 1) ^ 1][0][0];
        uint32_t af[4][4];
        {
            const uint4* p0 = (const uint4*)(hb + r * HSTR + q * 16);
            const uint4* p1 = (const uint4*)(hb + (r + 8) * HSTR + q * 16);
            #pragma unroll
            for (int m = 0; m < 2; ++m) {
                const uint4 v = p0[m];
                af[2*m][0] = v.x; af[2*m][2] = v.y; af[2*m+1][0] = v.z; af[2*m+1][2] = v.w;
                const uint4 u = p1[m];
                af[2*m][1] = u.x; af[2*m][3] = u.y; af[2*m+1][1] = u.z; af[2*m+1][3] = u.w;
            }
        }

        // ---- all 16 HMMA: 4 independent 4-deep chains ----
        float d[4][4] = {{0.f,0.f,0.f,0.f},{0.f,0.f,0.f,0.f},{0.f,0.f,0.f,0.f},{0.f,0.f,0.f,0.f}};
        #pragma unroll
        for (int ks = 0; ks < 4; ++ks) {
            mma16816(d[0], af[ks], bf[ks][0]);
            mma16816(d[1], af[ks], bf[ks][1]);
            mma16816(d[2], af[ks], bf[ks][2]);
            mma16816(d[3], af[ks], bf[ks][3]);
        }

        // ---- gates: sigmoid rows pre-scaled, sig = fma(0.5, tanh(z'), 0.5) ----
        __half* hw = &hs[t & 1][0][0];
        #pragma unroll
        for (int cidx = 0; cidx < 4; ++cidx) {
            const bool isU2 = cidx >= 2;
            const int ti = isU2 ? 2 : 0;
            const int co = (cidx & 1) * 2;
            const float xv = (cidx & 1) ? xv1 : xv0;
            const float zi = d[ti][co]     + fmaf(xv, isU2 ? wi_i2 : wi_i1, isU2 ? bi2 : bi1);
            const float zg = d[ti][co + 1] + fmaf(xv, isU2 ? wi_g2 : wi_g1, isU2 ? bg2 : bg1);
            const float zf = d[ti + 1][co]     + fmaf(xv, isU2 ? wi_f2 : wi_f1, isU2 ? bf2 : bf1);
            const float zo = d[ti + 1][co + 1] + fmaf(xv, isU2 ? wi_o2 : wi_o1, isU2 ? bo2 : bo1);
            const float ig = fmaf(0.5f, tanhapx(zi), 0.5f) * tanhapx(zg);
            const float ff = fmaf(0.5f, tanhapx(zf), 0.5f);
            cc[cidx] = fmaf(ff, cc[cidx], ig);
            hval[cidx] = fmaf(0.5f, tanhapx(zo), 0.5f) * tanhapx(cc[cidx]);
            hw[((cidx & 1) ? (r + 8) : r) * HSTR + (isU2 ? pc2 : pc1)] = __float2half_rn(hval[cidx]);
        }

        xv0 = pxv0;
        xv1 = pxv1;
        __syncthreads();
    }

    // ---- tail: reduce hval(T-1), flush T-2 and T-1 ----
    {
        float pr  = fcw1 * hval[0] + fcw2 * hval[2];
        float pr8 = fcw1 * hval[1] + fcw2 * hval[3];
        pr  += __shfl_xor_sync(0xffffffffu, pr, 1);
        pr  += __shfl_xor_sync(0xffffffffu, pr, 2);
        pr8 += __shfl_xor_sync(0xffffffffu, pr8, 1);
        pr8 += __shfl_xor_sync(0xffffffffu, pr8, 2);
        if (q == 0) {
            psum[(T_LEN - 1) & 1][r][wid] = pr;
            psum[(T_LEN - 1) & 1][r + 8][wid] = pr8;
        }
    }
    if (wid == 0 && lane < 16) {
        const float* ps = &psum[T_LEN & 1][lane][0];
        float s = 0.f;
        #pragma unroll
        for (int j = 0; j < 8; ++j) s += ps[j];
        atomicAdd(out + (size_t)(b0 + lane) * T_LEN + (T_LEN - 2), s);
    }
    __syncthreads();
    if (wid == 0 && lane < 16) {
        const float* ps = &psum[(T_LEN - 1) & 1][lane][0];
        float s = 0.f;
        #pragma unroll
        for (int j = 0; j < 8; ++j) s += ps[j];
        atomicAdd(out + (size_t)(b0 + lane) * T_LEN + (T_LEN - 1), s);
    }
}

extern "C" void kernel_launch(void* const* d_in, const int* in_sizes, int n_in,
                              void* d_out, int out_size) {
    const float* x     = (const float*)d_in[0];
    const float* Wih_f = (const float*)d_in[1];
    const float* Whh_f = (const float*)d_in[2];
    const float* bih_f = (const float*)d_in[3];
    const float* bhh_f = (const float*)d_in[4];
    const float* Wih_b = (const float*)d_in[5];
    const float* Whh_b = (const float*)d_in[6];
    const float* bih_b = (const float*)d_in[7];
    const float* bhh_b = (const float*)d_in[8];
    const float* fc_w  = (const float*)d_in[9];
    const float* fc_b  = (const float*)d_in[10];
    float* out = (float*)d_out;

    out_init<<<(out_size + 255) / 256, 256>>>(out, fc_b, out_size);

    const int B = in_sizes[0] / T_LEN;   // 1024
    const int grid = (B / 16) * 2;       // 128 CTAs: (batch-group, direction)
    bilstm_mma<<<grid, NTH>>>(x, Wih_f, Whh_f, bih_f, bhh_f,
                              Wih_b, Whh_b, bih_b, bhh_b, fc_w, out);
    (void)n_in;
}